// round 13
// baseline (speedup 1.0000x reference)
#include <cuda_runtime.h>
#include <cuda_bf16.h>
#include <cstdint>

#define BB 64
#define II 128
#define AA 16
#define HH 1024
#define BH (BB*HH)
#define LAG 3                       // plast chases state by 3 batches (~72MB window < L2)
#define NSLOT (BB + LAG)

// scratch (static __device__ — no allocations)
__device__ float g_sign[HH];            // column sign (+1 excitatory / -1 inhibitory)
__device__ unsigned int g_gq[HH*HH];    // packed bf16: lo = 0.02*|W_h|, hi = |kappa|
__device__ unsigned int g_cnt[BB];      // per-batch row-completion counters (1024 = done)

// ---------------- prep: pack (0.02*|W_h|, |kappa|) as bf16x2; sign; reset counters ----------------
__global__ void prep_gq(const float4* __restrict__ Wh, const float4* __restrict__ kap,
                        const float* __restrict__ mask) {
    int idx = blockIdx.x * blockDim.x + threadIdx.x;    // over HH*HH/8, 2 float4 each
    if (idx < BB) g_cnt[idx] = 0u;                      // reset barrier state every call
    if (idx < HH) {
        // mask_h[r, j] = sign_j for any r != j (zero diagonal) -> read row (j+1)%H
        g_sign[idx] = mask[((idx + 1) & (HH - 1)) * HH + idx];
    }
#pragma unroll
    for (int h = 0; h < 2; h++) {
        int e = idx + h * (HH * HH / 8);
        if (e >= HH * HH / 4) return;
        float4 wv = Wh[e];
        float4 kv = kap[e];
        uint4 o;
        o.x = (unsigned)__bfloat16_as_ushort(__float2bfloat16_rn(0.02f * fabsf(wv.x)))
            | ((unsigned)__bfloat16_as_ushort(__float2bfloat16_rn(fabsf(kv.x))) << 16);
        o.y = (unsigned)__bfloat16_as_ushort(__float2bfloat16_rn(0.02f * fabsf(wv.y)))
            | ((unsigned)__bfloat16_as_ushort(__float2bfloat16_rn(fabsf(kv.y))) << 16);
        o.z = (unsigned)__bfloat16_as_ushort(__float2bfloat16_rn(0.02f * fabsf(wv.z)))
            | ((unsigned)__bfloat16_as_ushort(__float2bfloat16_rn(fabsf(kv.z))) << 16);
        o.w = (unsigned)__bfloat16_as_ushort(__float2bfloat16_rn(0.02f * fabsf(wv.w)))
            | ((unsigned)__bfloat16_as_ushort(__float2bfloat16_rn(fabsf(kv.w))) << 16);
        ((uint4*)g_gq)[e] = o;
    }
}

// ---------------- pass-2 math on one float4 column chunk ----------------
__device__ __forceinline__ float4 plast4(float4 w, uint4 gq, float4 no, float coef) {
    float4 r;
    {
        float g = __bfloat162float(__ushort_as_bfloat16((unsigned short)(gq.x & 0xffff)));
        float q = __bfloat162float(__ushort_as_bfloat16((unsigned short)(gq.x >> 16)));
        r.x = fminf(fmaxf(g + 0.98f * w.x + coef * q * no.x, 0.f), 1.f);
    }
    {
        float g = __bfloat162float(__ushort_as_bfloat16((unsigned short)(gq.y & 0xffff)));
        float q = __bfloat162float(__ushort_as_bfloat16((unsigned short)(gq.y >> 16)));
        r.y = fminf(fmaxf(g + 0.98f * w.y + coef * q * no.y, 0.f), 1.f);
    }
    {
        float g = __bfloat162float(__ushort_as_bfloat16((unsigned short)(gq.z & 0xffff)));
        float q = __bfloat162float(__ushort_as_bfloat16((unsigned short)(gq.z >> 16)));
        r.z = fminf(fmaxf(g + 0.98f * w.z + coef * q * no.z, 0.f), 1.f);
    }
    {
        float g = __bfloat162float(__ushort_as_bfloat16((unsigned short)(gq.w & 0xffff)));
        float q = __bfloat162float(__ushort_as_bfloat16((unsigned short)(gq.w >> 16)));
        r.w = fminf(fmaxf(g + 0.98f * w.w + coef * q * no.w, 0.f), 1.f);
    }
    return r;
}

// ---------------- mega kernel: warps 0-3 = state(slot), warps 4-7 = plast(slot-LAG) ----------------
__global__ __launch_bounds__(256) void k_mega(const float* __restrict__ wh,
                                              const float* __restrict__ state,
                                              const float* __restrict__ outp,
                                              const float* __restrict__ x,
                                              const float* __restrict__ aux,
                                              const float* __restrict__ Wx,
                                              const float* __restrict__ Waux,
                                              const float* __restrict__ bh,
                                              const float* __restrict__ da,
                                              float* __restrict__ out_state,
                                              float* __restrict__ out_output,
                                              float* __restrict__ out_w) {
    const int slot = blockIdx.x >> 8;             // 256 blocks per slot
    const int sub  = blockIdx.x & 255;
    const int warp = threadIdx.x >> 5;
    const int lane = threadIdx.x & 31;
    const int i0 = sub * 4;                       // this block covers rows i0..i0+3

    if (warp < 4) {
        // ============ STATE: batch = slot, row = i0 + warp (warp-per-row) ============
        if (slot >= BB) return;
        const int b = slot;
        const int i = i0 + warp;
        const int row = (b << 10) + i;

        // feedforward partial (overlaps with wh DRAM loads below)
        float acc;
        {
            float4 wx4 = ((const float4*)(Wx + i * II))[lane];
            float4 xv  = ((const float4*)(x + b * II))[lane];
            acc = fmaxf(xv.x, 0.f) * fabsf(wx4.x) + fmaxf(xv.y, 0.f) * fabsf(wx4.y)
                + fmaxf(xv.z, 0.f) * fabsf(wx4.z) + fmaxf(xv.w, 0.f) * fabsf(wx4.w);
            if (lane < 4) {
                float4 wa = ((const float4*)(Waux + i * AA))[lane];
                float4 av = ((const float4*)(aux + b * AA))[lane];
                acc += fmaxf(av.x, 0.f) * fabsf(wa.x) + fmaxf(av.y, 0.f) * fabsf(wa.y)
                     + fmaxf(av.z, 0.f) * fabsf(wa.z) + fmaxf(av.w, 0.f) * fabsf(wa.w);
            }
        }

        // 8 front-batched independent DRAM loads (8KB in flight per warp)
        const float4* wr = (const float4*)(wh + (size_t)row * HH);
        float4 w[8];
#pragma unroll
        for (int k = 0; k < 8; k++) w[k] = wr[lane + 32 * k];

#pragma unroll
        for (int k = 0; k < 8; k++) {
            int j4 = lane + 32 * k;
            float4 sg = ((const float4*)g_sign)[j4];
            float4 ov = ((const float4*)(outp + (b << 10)))[j4];
            acc = fmaf(w[k].x, sg.x * ov.x, acc);
            acc = fmaf(w[k].y, sg.y * ov.y, acc);
            acc = fmaf(w[k].z, sg.z * ov.z, acc);
            acc = fmaf(w[k].w, sg.w * ov.w, acc);
        }

        // zero-diagonal: column i lives in float4 #sub -> lane sub&31, chunk sub>>5, comp = warp
        if (lane == (sub & 31)) {
            int k = sub >> 5;
            float wv = (warp == 0) ? w[k].x : (warp == 1) ? w[k].y : (warp == 2) ? w[k].z : w[k].w;
            float sv = g_sign[i] * outp[row];
            acc -= wv * sv;
        }
#pragma unroll
        for (int off = 16; off; off >>= 1) acc += __shfl_down_sync(0xffffffffu, acc, off);

        if (lane == 0) {
            float ns = 0.8f * state[row] + 0.2f * (acc + bh[i]);
            out_state[row] = ns;
            out_output[row] = ns > 0.f ? tanhf(ns) : 0.f;     // retanh
            // release-arrive: publishes this lane's two writes to acquirers of g_cnt
            asm volatile("red.release.gpu.global.add.u32 [%0], %1;"
                         :: "l"(g_cnt + b), "r"(1u) : "memory");
        }
    } else {
        // ============ PLAST: batch = slot - LAG, row = i0 + (warp-4) ============
        const int b = slot - LAG;
        if (b < 0) return;
        const int i = i0 + (warp - 4);
        const int row = (b << 10) + i;

        // spin until all 1024 rows of batch b are published (normally already true)
        if (lane == 0) {
            unsigned v;
            do {
                asm volatile("ld.global.acquire.gpu.u32 %0, [%1];" : "=r"(v) : "l"(g_cnt + b));
                if (v < 1024u) __nanosleep(64);
            } while (v < 1024u);
        }
        __syncwarp();

        const float coef = 0.02f * da[b] * __ldcg(out_output + row);
        const float* whr = wh + (size_t)row * HH;
        const unsigned* gqr = g_gq + i * HH;
        const float* nob = out_output + (b << 10);
        float* owr = out_w + (size_t)row * HH;

#pragma unroll
        for (int h = 0; h < 2; h++) {              // 2 halves x 4 chunks (MLP=12 per half)
            float4 wv[4]; uint4 gv[4]; float4 nv[4];
#pragma unroll
            for (int k = 0; k < 4; k++) {
                int j4 = lane + 32 * (4 * h + k);
                wv[k] = __ldcs((const float4*)whr + j4);   // L2 hit (chase), evict after
                gv[k] = *((const uint4*)gqr + j4);         // L2-resident table
                nv[k] = __ldcg((const float4*)nob + j4);   // cross-block data, bypass L1
            }
#pragma unroll
            for (int k = 0; k < 4; k++) {
                int j4 = lane + 32 * (4 * h + k);
                __stcs((float4*)owr + j4, plast4(wv[k], gv[k], nv[k], coef));
            }
        }
    }
}

extern "C" void kernel_launch(void* const* d_in, const int* in_sizes, int n_in,
                              void* d_out, int out_size) {
    const float* x      = (const float*)d_in[0];   // [B,I]
    const float* state  = (const float*)d_in[1];   // [B,H]
    const float* outp   = (const float*)d_in[2];   // [B,H]
    const float* wh     = (const float*)d_in[3];   // [B,H,H]
    const float* da     = (const float*)d_in[4];   // [B]
    const float* aux    = (const float*)d_in[5];   // [B,A]
    const float* Wx     = (const float*)d_in[6];   // [H,I]
    const float* Waux   = (const float*)d_in[7];   // [H,A]
    const float* Wh     = (const float*)d_in[8];   // [H,H]
    const float* bh     = (const float*)d_in[9];   // [H]
    const float* kappa  = (const float*)d_in[10];  // [H,H]
    const float* mask   = (const float*)d_in[11];  // [H,H]

    float* out_state  = (float*)d_out;                 // [B,H]
    float* out_output = (float*)d_out + BH;            // [B,H]
    float* out_w      = (float*)d_out + 2 * BH;        // [B,H,H]

    prep_gq<<<(HH * HH / 8 + 255) / 256, 256>>>((const float4*)Wh, (const float4*)kappa, mask);
    k_mega<<<NSLOT * 256, 256>>>(wh, state, outp, x, aux, Wx, Waux, bh, da,
                                 out_state, out_output, out_w);
}

// round 14
// speedup vs baseline: 2.0419x; 2.0419x over previous
#include <cuda_runtime.h>
#include <cuda_bf16.h>
#include <cstdint>

#define BB 64
#define II 128
#define AA 16
#define HH 1024
#define BH (BB*HH)
#define LAG 3                       // plast chases state by 3 batches (~50MB window << L2)
#define NSLOT (BB + LAG)

// scratch (static __device__ — no allocations)
__device__ float g_sign[HH];            // column sign (+1 excitatory / -1 inhibitory)
__device__ unsigned int g_gq[HH*HH];    // packed bf16: lo = 0.02*|W_h|, hi = |kappa|
__device__ unsigned int g_cnt[BB];      // per-batch state completion counters

// ---------------- prep: pack (0.02*|W_h|, |kappa|) as bf16x2; sign; reset counters ----------------
__global__ void prep_gq(const float4* __restrict__ Wh, const float4* __restrict__ kap,
                        const float* __restrict__ mask) {
    int idx = blockIdx.x * blockDim.x + threadIdx.x;    // over HH*HH/4
    if (idx < BB) g_cnt[idx] = 0u;                      // reset barrier state every call
    if (idx < HH) {
        // mask_h[r, j] = sign_j for any r != j (zero diagonal) -> read row (j+1)%H
        g_sign[idx] = mask[((idx + 1) & (HH - 1)) * HH + idx];
    }
    if (idx >= HH * HH / 4) return;
    float4 wv = Wh[idx];
    float4 kv = kap[idx];
    uint4 o;
    o.x = (unsigned)__bfloat16_as_ushort(__float2bfloat16_rn(0.02f * fabsf(wv.x)))
        | ((unsigned)__bfloat16_as_ushort(__float2bfloat16_rn(fabsf(kv.x))) << 16);
    o.y = (unsigned)__bfloat16_as_ushort(__float2bfloat16_rn(0.02f * fabsf(wv.y)))
        | ((unsigned)__bfloat16_as_ushort(__float2bfloat16_rn(fabsf(kv.y))) << 16);
    o.z = (unsigned)__bfloat16_as_ushort(__float2bfloat16_rn(0.02f * fabsf(wv.z)))
        | ((unsigned)__bfloat16_as_ushort(__float2bfloat16_rn(fabsf(kv.z))) << 16);
    o.w = (unsigned)__bfloat16_as_ushort(__float2bfloat16_rn(0.02f * fabsf(wv.w)))
        | ((unsigned)__bfloat16_as_ushort(__float2bfloat16_rn(fabsf(kv.w))) << 16);
    ((uint4*)g_gq)[idx] = o;
}

// ---------------- pass-2 math on one float4 column chunk ----------------
__device__ __forceinline__ float4 plast4(float4 w, uint4 gq, float4 no, float coef) {
    float4 r;
    {
        float g = __bfloat162float(__ushort_as_bfloat16((unsigned short)(gq.x & 0xffff)));
        float q = __bfloat162float(__ushort_as_bfloat16((unsigned short)(gq.x >> 16)));
        r.x = fminf(fmaxf(g + 0.98f * w.x + coef * q * no.x, 0.f), 1.f);
    }
    {
        float g = __bfloat162float(__ushort_as_bfloat16((unsigned short)(gq.y & 0xffff)));
        float q = __bfloat162float(__ushort_as_bfloat16((unsigned short)(gq.y >> 16)));
        r.y = fminf(fmaxf(g + 0.98f * w.y + coef * q * no.y, 0.f), 1.f);
    }
    {
        float g = __bfloat162float(__ushort_as_bfloat16((unsigned short)(gq.z & 0xffff)));
        float q = __bfloat162float(__ushort_as_bfloat16((unsigned short)(gq.z >> 16)));
        r.z = fminf(fmaxf(g + 0.98f * w.z + coef * q * no.z, 0.f), 1.f);
    }
    {
        float g = __bfloat162float(__ushort_as_bfloat16((unsigned short)(gq.w & 0xffff)));
        float q = __bfloat162float(__ushort_as_bfloat16((unsigned short)(gq.w >> 16)));
        r.w = fminf(fmaxf(g + 0.98f * w.w + coef * q * no.w, 0.f), 1.f);
    }
    return r;
}

// ---------------- mega kernel: state(slot) + plast(slot-LAG), reads merged up front ----------------
__global__ __launch_bounds__(256) void k_mega(const float* __restrict__ wh,
                                              const float* __restrict__ state,
                                              const float* __restrict__ outp,
                                              const float* __restrict__ x,
                                              const float* __restrict__ aux,
                                              const float* __restrict__ Wx,
                                              const float* __restrict__ Waux,
                                              const float* __restrict__ bh,
                                              const float* __restrict__ da,
                                              float* __restrict__ out_state,
                                              float* __restrict__ out_output,
                                              float* __restrict__ out_w) {
    const int slot = blockIdx.x >> 8;             // 256 blocks per slot
    const int sub  = blockIdx.x & 255;
    const int t = threadIdx.x;
    const int warp = t >> 5;
    const int lane = t & 31;
    const int i0 = sub * 4;                       // rows i0..i0+3 (both phases)
    __shared__ float red[8 * 4];
    __shared__ float ff_sh[4];

    const int bp = slot - LAG;                    // plast batch (may be <0 / >=BB)
    const bool do_state = (slot < BB);
    const bool do_plast = (bp >= 0);

    // ===== merged read epoch: phase-1 DRAM loads + phase-2 L2 loads, all front-batched =====
    float4 w0, w1, w2, w3;                        // state wh rows (DRAM)
    if (do_state) {
        const float4* wp = (const float4*)(wh + ((size_t)(slot << 10) + i0) * HH) + t;
        w0 = wp[0]; w1 = wp[256]; w2 = wp[512]; w3 = wp[768];
    }
    float4 wA, wB, wC, wD;                        // plast wh rows (L2 hits via chase)
    size_t baseP = 0;
    if (do_plast) {
        baseP = ((size_t)(bp << 10) + i0) * HH + 4 * t;
        wA = __ldcs((const float4*)(wh + baseP));
        wB = __ldcs((const float4*)(wh + baseP + HH));
        wC = __ldcs((const float4*)(wh + baseP + 2 * HH));
        wD = __ldcs((const float4*)(wh + baseP + 3 * HH));
    }

    // ================= phase 1: STATE for batch = slot =================
    if (do_state) {
        const int b = slot;
        const int row0 = (b << 10) + i0;

        float4 sg = ((const float4*)g_sign)[t];
        float4 ov = ((const float4*)(outp + (b << 10)))[t];
        float4 s = make_float4(sg.x * ov.x, sg.y * ov.y, sg.z * ov.z, sg.w * ov.w);

        if (warp < 4) {                           // ff while loads are in flight
            int i = i0 + warp;
            float4 w = ((const float4*)(Wx + i * II))[lane];
            float4 xv = ((const float4*)(x + b * II))[lane];
            float acc = fmaxf(xv.x, 0.f) * fabsf(w.x) + fmaxf(xv.y, 0.f) * fabsf(w.y)
                      + fmaxf(xv.z, 0.f) * fabsf(w.z) + fmaxf(xv.w, 0.f) * fabsf(w.w);
            if (lane < 4) {
                float4 wa = ((const float4*)(Waux + i * AA))[lane];
                float4 av = ((const float4*)(aux + b * AA))[lane];
                acc += fmaxf(av.x, 0.f) * fabsf(wa.x) + fmaxf(av.y, 0.f) * fabsf(wa.y)
                     + fmaxf(av.z, 0.f) * fabsf(wa.z) + fmaxf(av.w, 0.f) * fabsf(wa.w);
            }
#pragma unroll
            for (int off = 16; off; off >>= 1) acc += __shfl_down_sync(0xffffffffu, acc, off);
            if (lane == 0) ff_sh[warp] = acc + bh[i];
        }

        float a0 = w0.x * s.x + w0.y * s.y + w0.z * s.z + w0.w * s.w;
        float a1 = w1.x * s.x + w1.y * s.y + w1.z * s.z + w1.w * s.w;
        float a2 = w2.x * s.x + w2.y * s.y + w2.z * s.z + w2.w * s.w;
        float a3 = w3.x * s.x + w3.y * s.y + w3.z * s.z + w3.w * s.w;

#pragma unroll
        for (int r = 0; r < 4; r++) {             // zero-diagonal fixups
            int i = i0 + r;
            if (t == (i >> 2)) {
                int c = i & 3;
                float4 w = (r == 0) ? w0 : (r == 1) ? w1 : (r == 2) ? w2 : w3;
                float wv = (c == 0) ? w.x : (c == 1) ? w.y : (c == 2) ? w.z : w.w;
                float sv = (c == 0) ? s.x : (c == 1) ? s.y : (c == 2) ? s.z : s.w;
                float d = wv * sv;
                if (r == 0) a0 -= d; else if (r == 1) a1 -= d; else if (r == 2) a2 -= d; else a3 -= d;
            }
        }
#pragma unroll
        for (int off = 16; off; off >>= 1) {
            a0 += __shfl_down_sync(0xffffffffu, a0, off);
            a1 += __shfl_down_sync(0xffffffffu, a1, off);
            a2 += __shfl_down_sync(0xffffffffu, a2, off);
            a3 += __shfl_down_sync(0xffffffffu, a3, off);
        }
        if (lane == 0) {
            red[warp * 4 + 0] = a0; red[warp * 4 + 1] = a1;
            red[warp * 4 + 2] = a2; red[warp * 4 + 3] = a3;
        }
        __syncthreads();
        if (t < 4) {
            float total = ff_sh[t];
#pragma unroll
            for (int w = 0; w < 8; w++) total += red[w * 4 + t];
            float ns = 0.8f * state[row0 + t] + 0.2f * total;
            out_state[row0 + t] = ns;
            out_output[row0 + t] = ns > 0.f ? tanhf(ns) : 0.f;   // retanh
            __threadfence();                       // publish before arrive
        }
        __syncthreads();
        if (t == 0) atomicAdd(&g_cnt[slot], 1u);   // signal: this block's 4 rows done
    }

    // ================= phase 2: PLAST for batch = slot - LAG =================
    if (do_plast) {
        const int b = bp;
        const int row0 = (b << 10) + i0;

        if (t == 0) {                              // pre-satisfied at LAG=3
            unsigned v;
            do {
                asm volatile("ld.global.acquire.gpu.u32 %0, [%1];" : "=r"(v) : "l"(g_cnt + b));
                if (v < 256u) __nanosleep(100);
            } while (v < 256u);
        }
        __syncthreads();

        const float dab = 0.02f * da[b];
        const float c0 = dab * __ldcg(out_output + row0);
        const float c1 = dab * __ldcg(out_output + row0 + 1);
        const float c2 = dab * __ldcg(out_output + row0 + 2);
        const float c3 = dab * __ldcg(out_output + row0 + 3);

        float4 no = __ldcg((const float4*)(out_output + (b << 10) + 4 * t));  // bypass L1
        const unsigned* gqp = g_gq + i0 * HH + 4 * t;

        {
            uint4 gA = *(const uint4*)(gqp);
            uint4 gB = *(const uint4*)(gqp + HH);
            __stcs((float4*)(out_w + baseP),      plast4(wA, gA, no, c0));
            __stcs((float4*)(out_w + baseP + HH), plast4(wB, gB, no, c1));
        }
        {
            uint4 gC = *(const uint4*)(gqp + 2 * HH);
            uint4 gD = *(const uint4*)(gqp + 3 * HH);
            __stcs((float4*)(out_w + baseP + 2 * HH), plast4(wC, gC, no, c2));
            __stcs((float4*)(out_w + baseP + 3 * HH), plast4(wD, gD, no, c3));
        }
    }
}

extern "C" void kernel_launch(void* const* d_in, const int* in_sizes, int n_in,
                              void* d_out, int out_size) {
    const float* x      = (const float*)d_in[0];   // [B,I]
    const float* state  = (const float*)d_in[1];   // [B,H]
    const float* outp   = (const float*)d_in[2];   // [B,H]
    const float* wh     = (const float*)d_in[3];   // [B,H,H]
    const float* da     = (const float*)d_in[4];   // [B]
    const float* aux    = (const float*)d_in[5];   // [B,A]
    const float* Wx     = (const float*)d_in[6];   // [H,I]
    const float* Waux   = (const float*)d_in[7];   // [H,A]
    const float* Wh     = (const float*)d_in[8];   // [H,H]
    const float* bh     = (const float*)d_in[9];   // [H]
    const float* kappa  = (const float*)d_in[10];  // [H,H]
    const float* mask   = (const float*)d_in[11];  // [H,H]

    float* out_state  = (float*)d_out;                 // [B,H]
    float* out_output = (float*)d_out + BH;            // [B,H]
    float* out_w      = (float*)d_out + 2 * BH;        // [B,H,H]

    prep_gq<<<(HH * HH / 4 + 255) / 256, 256>>>((const float4*)Wh, (const float4*)kappa, mask);
    k_mega<<<NSLOT * 256, 256>>>(wh, state, outp, x, aux, Wx, Waux, bh, da,
                                 out_state, out_output, out_w);
}